// round 4
// baseline (speedup 1.0000x reference)
#include <cuda_runtime.h>
#include <math.h>

#define SEQ   128
#define BATCH 512
#define INDIM 128
#define HID   128
#define FULLM 0xffffffffu

__device__ __forceinline__ float sigmoid_f(float x) {
    return __fdividef(1.f, 1.f + __expf(-x));
}
__device__ __forceinline__ float tanh_f(float x) {
    // tanh(x) = 1 - 2/(1+e^{2x}); saturates correctly at +/-inf
    return 1.f - 2.f * __fdividef(1.f, 1.f + __expf(2.f * x));
}

// 512 blocks (one per batch element), 256 threads = 8 warps.
// Warp wp = (comp, g): g = wp&3 selects gate type (f,i,g,o), comp = wp>>2
// selects real (0) or imag (1) component of the statevector. The circuit
// after RX encoding is real, so both components evolve independently.
// Each warp holds one real 256-vector: index i = r*32 + lane.
__global__ __launch_bounds__(256, 4)
void qlstm_kernel(const float* __restrict__ inputs,
                  const float* __restrict__ Wq,  const float* __restrict__ bq,
                  const float* __restrict__ pf,  const float* __restrict__ pi_,
                  const float* __restrict__ pg,  const float* __restrict__ po,
                  const float* __restrict__ Wfp, const float* __restrict__ bf,
                  const float* __restrict__ Wip, const float* __restrict__ bi,
                  const float* __restrict__ Wgp, const float* __restrict__ bg,
                  const float* __restrict__ Wop, const float* __restrict__ bo,
                  float* __restrict__ out)
{
    __shared__ float sWq[8][256];      // rows 0..7 of Wq (only ones used)
    __shared__ float sWT[4][8][128];   // gate weights transposed [g][w][hid]
    __shared__ float sb[4][128];       // gate biases
    __shared__ float sbq[8];
    __shared__ float rc[4][2][8], rs[4][2][8];   // RY half-angle cos/sin
    __shared__ float comb[256];        // [ x_t | h ]
    __shared__ float cth[8], sth[8];   // RX half-angle cos/sin
    __shared__ float zz2[4][8][2];     // per-component partial <Z_w>
    __shared__ float zzs[4][8];        // combined <Z_w>

    const int tid  = threadIdx.x;
    const int lane = tid & 31;
    const int wp   = tid >> 5;
    const int g    = wp & 3;
    const int comp = wp >> 2;
    const int b    = blockIdx.x;

    // ---- stage weights ----
    for (int i = tid; i < 8 * 256; i += 256) sWq[i >> 8][i & 255] = Wq[i];
    {
        const float* W4[4] = {Wfp, Wip, Wgp, Wop};
        const float* b4[4] = {bf, bi, bg, bo};
        const float* p4[4] = {pf, pi_, pg, po};
        for (int gg = 0; gg < 4; gg++) {
            for (int i = tid; i < 1024; i += 256) sWT[gg][i & 7][i >> 3] = W4[gg][i];
            if (tid < 128) sb[gg][tid] = b4[gg][tid];
            if (tid < 16) {
                float a = 0.5f * p4[gg][tid];
                rc[gg][tid >> 3][tid & 7] = cosf(a);
                rs[gg][tid >> 3][tid & 7] = sinf(a);
            }
        }
    }
    if (tid < 8) sbq[tid] = bq[tid];
    if (tid < 128) comb[128 + tid] = 0.f;               // h0
    else           comb[tid - 128] = inputs[(size_t)b * INDIM + (tid - 128)]; // x_0
    float c_reg = 0.f;                                   // cell state (tid<128)
    __syncthreads();

    const int bsl = lane ^ (lane >> 1);
    const int lpc = __popc(lane);

    for (int t = 0; t < SEQ; t++) {
        // ---- phase B: q_in row = wp (one row per warp, 8 rows total) ----
        {
            float sum = 0.f;
            #pragma unroll
            for (int k = 0; k < 8; k++)
                sum = fmaf(sWq[wp][lane + 32 * k], comb[lane + 32 * k], sum);
            #pragma unroll
            for (int off = 16; off; off >>= 1)
                sum += __shfl_xor_sync(FULLM, sum, off);
            if (lane == 0) {
                float a = 0.5f * (sum + sbq[wp]);
                float s, c;
                sincosf(a, &s, &c);
                cth[wp] = c; sth[wp] = s;
            }
        }
        __syncthreads();

        // ---- phase C: real-component statevector sim ----
        {
            float v[8];
            // psi0: product state, (-i)^popc split into re/im supports
            float lanep = 1.f;
            #pragma unroll
            for (int k = 0; k < 5; k++)
                lanep *= ((lane >> k) & 1) ? sth[7 - k] : cth[7 - k];
            #pragma unroll
            for (int r = 0; r < 8; r++) {
                float mag = lanep;
                #pragma unroll
                for (int k = 0; k < 3; k++)
                    mag *= ((r >> k) & 1) ? sth[2 - k] : cth[2 - k];
                int kk = (lpc + __popc(r)) & 3;
                float val;
                if (comp == 0) val = (kk == 0) ? mag : ((kk == 2) ? -mag : 0.f);
                else           val = (kk == 1) ? -mag : ((kk == 3) ? mag : 0.f);
                v[r] = val;
            }

            #pragma unroll
            for (int d = 0; d < 2; d++) {
                #pragma unroll
                for (int w = 0; w < 8; w++) {
                    const float c = rc[g][d][w], s = rs[g][d][w];
                    if (w <= 2) {
                        const int rb = 2 - w;
                        #pragma unroll
                        for (int r0 = 0; r0 < 8; r0++) {
                            if (!((r0 >> rb) & 1)) {
                                const int r1 = r0 | (1 << rb);
                                float a0 = v[r0], a1 = v[r1];
                                v[r0] = fmaf(c, a0, -s * a1);
                                v[r1] = fmaf(s, a0,  c * a1);
                            }
                        }
                    } else {
                        const int pb = 7 - w;
                        const int m = 1 << pb;
                        const float sg = ((lane >> pb) & 1) ? s : -s;
                        #pragma unroll
                        for (int r = 0; r < 8; r++) {
                            float pv = __shfl_xor_sync(FULLM, v[r], m);
                            v[r] = fmaf(c, v[r], sg * pv);
                        }
                    }
                }
                if (d == 0) {
                    // CNOT ladder permutation new[r'] = old[r'^(r'>>1)] with
                    // lane shuffle; done in cycle order, minimal temps.
                    v[0] = __shfl_sync(FULLM, v[0], bsl);
                    v[1] = __shfl_sync(FULLM, v[1], bsl ^ 16);
                    float t3 = __shfl_sync(FULLM, v[2], bsl ^ 16);  // new3 = old2
                    v[2] = __shfl_sync(FULLM, v[3], bsl);           // new2 = old3
                    v[3] = t3;
                    float t7 = __shfl_sync(FULLM, v[4], bsl ^ 16);  // new7 = old4
                    v[4] = __shfl_sync(FULLM, v[6], bsl);           // new4 = old6
                    v[6] = __shfl_sync(FULLM, v[5], bsl);           // new6 = old5
                    v[5] = __shfl_sync(FULLM, v[7], bsl ^ 16);      // new5 = old7
                    v[7] = t7;
                }
            }

            // measurement (second CNOT ladder folded into signs)
            float p[8];
            #pragma unroll
            for (int r = 0; r < 8; r++) p[r] = v[r] * v[r];

            // d = sum_r (-1)^popc(r) p[r]   (also = <Z_2> pre-lane-reduce)
            float d0 = ((p[0] - p[1]) - (p[2] - p[3])) - ((p[4] - p[5]) - (p[6] - p[7]));
            // w=0: sign (-1)^{b2}; w=1: sign (-1)^{b2^b1}
            float a0 = (p[0] + p[1] + p[2] + p[3]) - (p[4] + p[5] + p[6] + p[7]);
            float a1 = (p[0] + p[1] + p[6] + p[7]) - (p[2] + p[3] + p[4] + p[5]);

            #pragma unroll
            for (int off = 16; off; off >>= 1) {
                a0 += __shfl_xor_sync(FULLM, a0, off);
                a1 += __shfl_xor_sync(FULLM, a1, off);
            }
            // FWHT: lane m ends with W_m = sum_l (-1)^{popc(l&m)} d_l
            #pragma unroll
            for (int k = 0; k < 5; k++) {
                float pv = __shfl_xor_sync(FULLM, d0, 1 << k);
                d0 = ((lane >> k) & 1) ? pv - d0 : pv + d0;
            }
            // suffix masks: w=3..7 live at lanes 16,24,28,30,31; w=2 at lane 0
            if (lane == 0)  { zz2[g][0][comp] = a0; zz2[g][1][comp] = a1; zz2[g][2][comp] = d0; }
            if (lane == 16)   zz2[g][3][comp] = d0;
            if (lane == 24)   zz2[g][4][comp] = d0;
            if (lane == 28)   zz2[g][5][comp] = d0;
            if (lane == 30)   zz2[g][6][comp] = d0;
            if (lane == 31)   zz2[g][7][comp] = d0;
        }
        __syncthreads();

        // ---- combine re/im partials ----
        if (tid < 32)
            zzs[tid >> 3][tid & 7] = zz2[tid >> 3][tid & 7][0] + zz2[tid >> 3][tid & 7][1];
        __syncthreads();

        // ---- phase D (warps 0-3) || x_{t+1} prefetch (warps 4-7) ----
        if (tid < 128) {
            const int hd = tid;
            float zf = sb[0][hd], zi = sb[1][hd], zg = sb[2][hd], zo = sb[3][hd];
            #pragma unroll
            for (int w = 0; w < 8; w++) {
                zf = fmaf(sWT[0][w][hd], zzs[0][w], zf);
                zi = fmaf(sWT[1][w][hd], zzs[1][w], zi);
                zg = fmaf(sWT[2][w][hd], zzs[2][w], zg);
                zo = fmaf(sWT[3][w][hd], zzs[3][w], zo);
            }
            float f  = sigmoid_f(zf);
            float ii = sigmoid_f(zi);
            float gg = tanh_f(zg);
            float oo = sigmoid_f(zo);
            float cn = fmaf(f, c_reg, ii * gg);
            float hn = oo * tanh_f(cn);
            out[((size_t)t * BATCH + b) * HID + hd] = hn;
            c_reg = cn;
            comb[128 + hd] = hn;
        } else if (t + 1 < SEQ) {
            comb[tid - 128] = inputs[((size_t)(t + 1) * BATCH + b) * INDIM + (tid - 128)];
        }
        __syncthreads();
    }

    // final hx, cx
    if (tid < 128) {
        out[(size_t)SEQ * BATCH * HID + (size_t)b * HID + tid]               = comb[128 + tid];
        out[(size_t)SEQ * BATCH * HID + (size_t)BATCH * HID + (size_t)b * HID + tid] = c_reg;
    }
}

extern "C" void kernel_launch(void* const* d_in, const int* in_sizes, int n_in,
                              void* d_out, int out_size) {
    const float* inputs = (const float*)d_in[0];
    const float* Wq  = (const float*)d_in[1];
    const float* bq  = (const float*)d_in[2];
    const float* pf  = (const float*)d_in[3];
    const float* pi_ = (const float*)d_in[4];
    const float* pg  = (const float*)d_in[5];
    const float* po  = (const float*)d_in[6];
    const float* Wf  = (const float*)d_in[7];
    const float* bf  = (const float*)d_in[8];
    const float* Wi  = (const float*)d_in[9];
    const float* bi  = (const float*)d_in[10];
    const float* Wg  = (const float*)d_in[11];
    const float* bg  = (const float*)d_in[12];
    const float* Wo  = (const float*)d_in[13];
    const float* bo  = (const float*)d_in[14];

    qlstm_kernel<<<BATCH, 256>>>(inputs, Wq, bq, pf, pi_, pg, po,
                                 Wf, bf, Wi, bi, Wg, bg, Wo, bo,
                                 (float*)d_out);
}

// round 8
// speedup vs baseline: 1.1746x; 1.1746x over previous
#include <cuda_runtime.h>
#include <math.h>

#define SEQ   128
#define BATCH 512
#define INDIM 128
#define HID   128
#define FULLM 0xffffffffu

__device__ __forceinline__ float sigmoid_f(float x) {
    return __fdividef(1.f, 1.f + __expf(-x));
}
__device__ __forceinline__ float tanh_f(float x) {
    return 1.f - 2.f * __fdividef(1.f, 1.f + __expf(2.f * x));
}

// 512 blocks (one per batch element), 256 threads = 8 warps.
// Warp wp = (comp, g): g = wp&3 gate type (f,i,g,o), comp = wp>>2 selects
// real/imag statevector component (circuit after state prep is real, so the
// components evolve independently).
// Key algebraic fold: RY(layer0)*RX(enc)|0> is still a PRODUCT state:
//   u0(w) = (cp*ct,  sp*st),  u1(w) = (sp*ct, -cp*st)   [(re,im), half-angles]
// so the whole first RY layer is built in closed form — no shuffles.
__global__ __launch_bounds__(256, 4)
void qlstm_kernel(const float* __restrict__ inputs,
                  const float* __restrict__ Wq,  const float* __restrict__ bq,
                  const float* __restrict__ pf,  const float* __restrict__ pi_,
                  const float* __restrict__ pg,  const float* __restrict__ po,
                  const float* __restrict__ Wfp, const float* __restrict__ bf,
                  const float* __restrict__ Wip, const float* __restrict__ bi,
                  const float* __restrict__ Wgp, const float* __restrict__ bg,
                  const float* __restrict__ Wop, const float* __restrict__ bo,
                  float* __restrict__ out)
{
    __shared__ float sWq[8][256];
    __shared__ float sWT[4][8][128];
    __shared__ float sb[4][128];
    __shared__ float sbq[8];
    __shared__ float rc[4][2][8], rs[4][2][8];
    __shared__ float comb[256];        // [ x_t | h ]
    __shared__ float cth[8], sth[8];   // RX half-angle cos/sin (per step)
    __shared__ float zz2[4][8][2];     // per-component partial <Z_w>

    const int tid  = threadIdx.x;
    const int lane = tid & 31;
    const int wp   = tid >> 5;
    const int g    = wp & 3;
    const int comp = wp >> 2;
    const int b    = blockIdx.x;

    // ---- stage weights ----
    for (int i = tid; i < 8 * 256; i += 256) sWq[i >> 8][i & 255] = Wq[i];
    {
        const float* W4[4] = {Wfp, Wip, Wgp, Wop};
        const float* b4[4] = {bf, bi, bg, bo};
        const float* p4[4] = {pf, pi_, pg, po};
        for (int gg = 0; gg < 4; gg++) {
            for (int i = tid; i < 1024; i += 256) sWT[gg][i & 7][i >> 3] = W4[gg][i];
            if (tid < 128) sb[gg][tid] = b4[gg][tid];
            if (tid < 16) {
                float a = 0.5f * p4[gg][tid];
                rc[gg][tid >> 3][tid & 7] = cosf(a);
                rs[gg][tid >> 3][tid & 7] = sinf(a);
            }
        }
    }
    if (tid < 8) sbq[tid] = bq[tid];
    if (tid < 128) comb[128 + tid] = 0.f;                                      // h0
    else           comb[tid - 128] = inputs[(size_t)b * INDIM + (tid - 128)];  // x_0
    float c_reg = 0.f;
    __syncthreads();

    const int bsl = lane ^ (lane >> 1);

    for (int t = 0; t < SEQ; t++) {
        // ---- phase B: q_in row = wp (one row per warp) ----
        {
            float sum = 0.f;
            #pragma unroll
            for (int k = 0; k < 8; k++)
                sum = fmaf(sWq[wp][lane + 32 * k], comb[lane + 32 * k], sum);
            #pragma unroll
            for (int off = 16; off; off >>= 1)
                sum += __shfl_xor_sync(FULLM, sum, off);
            if (lane == 0) {
                float a = 0.5f * (sum + sbq[wp]);
                float s, c;
                __sincosf(a, &s, &c);
                cth[wp] = c; sth[wp] = s;
            }
        }
        __syncthreads();

        // ---- phase C: statevector sim (RY1 folded into product init) ----
        {
            float v[8];
            // lane-bit product over wires 7..3 (lane bits 0..4), complex
            float lre = 1.f, lim = 0.f;
            #pragma unroll
            for (int k = 0; k < 5; k++) {
                const int w = 7 - k;
                const float cp = rc[g][0][w], sp = rs[g][0][w];
                const float ct = cth[w], st = sth[w];
                const int bit = (lane >> k) & 1;
                const float ure = (bit ? sp : cp) * ct;
                const float uim = bit ? (-cp * st) : (sp * st);
                const float nre = lre * ure - lim * uim;
                const float nim = lre * uim + lim * ure;
                lre = nre; lim = nim;
            }
            // register-bit factors: r bit j -> wire (2-j)
            {
                float u_re[3][2], u_im[3][2];
                #pragma unroll
                for (int j = 0; j < 3; j++) {
                    const int w = 2 - j;
                    const float cp = rc[g][0][w], sp = rs[g][0][w];
                    const float ct = cth[w], st = sth[w];
                    u_re[j][0] = cp * ct;  u_im[j][0] = sp * st;
                    u_re[j][1] = sp * ct;  u_im[j][1] = -cp * st;
                }
                #pragma unroll
                for (int r = 0; r < 8; r++) {
                    const float are = u_re[0][r & 1],        aim = u_im[0][r & 1];
                    const float bre = u_re[1][(r >> 1) & 1], bim = u_im[1][(r >> 1) & 1];
                    const float tre = are * bre - aim * bim;
                    const float tim = are * bim + aim * bre;
                    const float cre = u_re[2][(r >> 2) & 1], cim = u_im[2][(r >> 2) & 1];
                    const float pre = tre * cre - tim * cim;
                    const float pim = tre * cim + tim * cre;
                    v[r] = (comp == 0) ? (lre * pre - lim * pim)
                                       : (lre * pim + lim * pre);
                }
            }

            // CNOT ladder 1: new[i] = old[i ^ (i>>1)]
            v[0] = __shfl_sync(FULLM, v[0], bsl);
            v[1] = __shfl_sync(FULLM, v[1], bsl ^ 16);
            float t3 = __shfl_sync(FULLM, v[2], bsl ^ 16);
            v[2] = __shfl_sync(FULLM, v[3], bsl);
            v[3] = t3;
            float t7 = __shfl_sync(FULLM, v[4], bsl ^ 16);
            v[4] = __shfl_sync(FULLM, v[6], bsl);
            v[6] = __shfl_sync(FULLM, v[5], bsl);
            v[5] = __shfl_sync(FULLM, v[7], bsl ^ 16);
            v[7] = t7;

            // RY layer 2
            #pragma unroll
            for (int w = 0; w < 8; w++) {
                const float c = rc[g][1][w], s = rs[g][1][w];
                if (w <= 2) {
                    const int rb = 2 - w;
                    #pragma unroll
                    for (int r0 = 0; r0 < 8; r0++) {
                        if (!((r0 >> rb) & 1)) {
                            const int r1 = r0 | (1 << rb);
                            const float a0 = v[r0], a1 = v[r1];
                            v[r0] = fmaf(c, a0, -s * a1);
                            v[r1] = fmaf(s, a0,  c * a1);
                        }
                    }
                } else {
                    const int pb = 7 - w;
                    const int m = 1 << pb;
                    const float sg = ((lane >> pb) & 1) ? s : -s;
                    #pragma unroll
                    for (int r = 0; r < 8; r++) {
                        const float pv = __shfl_xor_sync(FULLM, v[r], m);
                        v[r] = fmaf(c, v[r], sg * pv);
                    }
                }
            }

            // measurement (CNOT ladder 2 folded into signs)
            float p[8];
            #pragma unroll
            for (int r = 0; r < 8; r++) p[r] = v[r] * v[r];

            float d0 = ((p[0] - p[1]) - (p[2] - p[3])) - ((p[4] - p[5]) - (p[6] - p[7]));
            float a0 = (p[0] + p[1] + p[2] + p[3]) - (p[4] + p[5] + p[6] + p[7]);
            float a1 = (p[0] + p[1] + p[6] + p[7]) - (p[2] + p[3] + p[4] + p[5]);

            #pragma unroll
            for (int off = 16; off; off >>= 1) {
                a0 += __shfl_xor_sync(FULLM, a0, off);
                a1 += __shfl_xor_sync(FULLM, a1, off);
            }
            #pragma unroll
            for (int k = 0; k < 5; k++) {
                const float pv = __shfl_xor_sync(FULLM, d0, 1 << k);
                d0 = ((lane >> k) & 1) ? pv - d0 : pv + d0;
            }
            if (lane == 0)  { zz2[g][0][comp] = a0; zz2[g][1][comp] = a1; zz2[g][2][comp] = d0; }
            if (lane == 16)   zz2[g][3][comp] = d0;
            if (lane == 24)   zz2[g][4][comp] = d0;
            if (lane == 28)   zz2[g][5][comp] = d0;
            if (lane == 30)   zz2[g][6][comp] = d0;
            if (lane == 31)   zz2[g][7][comp] = d0;
        }
        __syncthreads();

        // ---- phase D (warps 0-3, re+im combined inline) || prefetch (4-7) ----
        if (tid < 128) {
            const int hd = tid;
            float zf = sb[0][hd], zi = sb[1][hd], zg = sb[2][hd], zo = sb[3][hd];
            #pragma unroll
            for (int w = 0; w < 8; w++) {
                zf = fmaf(sWT[0][w][hd], zz2[0][w][0] + zz2[0][w][1], zf);
                zi = fmaf(sWT[1][w][hd], zz2[1][w][0] + zz2[1][w][1], zi);
                zg = fmaf(sWT[2][w][hd], zz2[2][w][0] + zz2[2][w][1], zg);
                zo = fmaf(sWT[3][w][hd], zz2[3][w][0] + zz2[3][w][1], zo);
            }
            const float f  = sigmoid_f(zf);
            const float ii = sigmoid_f(zi);
            const float gg = tanh_f(zg);
            const float oo = sigmoid_f(zo);
            const float cn = fmaf(f, c_reg, ii * gg);
            const float hn = oo * tanh_f(cn);
            out[((size_t)t * BATCH + b) * HID + hd] = hn;
            c_reg = cn;
            comb[128 + hd] = hn;
        } else if (t + 1 < SEQ) {
            comb[tid - 128] = inputs[((size_t)(t + 1) * BATCH + b) * INDIM + (tid - 128)];
        }
        __syncthreads();
    }

    if (tid < 128) {
        out[(size_t)SEQ * BATCH * HID + (size_t)b * HID + tid]                       = comb[128 + tid];
        out[(size_t)SEQ * BATCH * HID + (size_t)BATCH * HID + (size_t)b * HID + tid] = c_reg;
    }
}

extern "C" void kernel_launch(void* const* d_in, const int* in_sizes, int n_in,
                              void* d_out, int out_size) {
    const float* inputs = (const float*)d_in[0];
    const float* Wq  = (const float*)d_in[1];
    const float* bq  = (const float*)d_in[2];
    const float* pf  = (const float*)d_in[3];
    const float* pi_ = (const float*)d_in[4];
    const float* pg  = (const float*)d_in[5];
    const float* po  = (const float*)d_in[6];
    const float* Wf  = (const float*)d_in[7];
    const float* bf  = (const float*)d_in[8];
    const float* Wi  = (const float*)d_in[9];
    const float* bi  = (const float*)d_in[10];
    const float* Wg  = (const float*)d_in[11];
    const float* bg  = (const float*)d_in[12];
    const float* Wo  = (const float*)d_in[13];
    const float* bo  = (const float*)d_in[14];

    qlstm_kernel<<<BATCH, 256>>>(inputs, Wq, bq, pf, pi_, pg, po,
                                 Wf, bf, Wi, bi, Wg, bg, Wo, bo,
                                 (float*)d_out);
}